// round 15
// baseline (speedup 1.0000x reference)
#include <cuda_runtime.h>
#include <cuda_bf16.h>
#include <math.h>
#include <stdint.h>

// Problem constants
#define NTOK   2048       // B*N
#define DDIM   1024
#define QDIM   2048       // 2*H*KD
#define NHEAD  8
#define KDIM   128
#define NKEYS  256
#define TOPK   16

// -------- scratch (device globals; no runtime allocation) --------
__device__ float g_cs[DDIM];
__device__ float g_cb[DDIM];
__device__ float g_qbias[QDIM];
__device__ float g_xT[(size_t)DDIM * NTOK];
__device__ float g_wq2[(size_t)DDIM * QDIM];
__device__ float g_qT[(size_t)QDIM * NTOK];
__device__ float g_kT[(size_t)NHEAD * 2 * KDIM * NKEYS];
__device__ float g_scores[(size_t)NTOK * NHEAD * TOPK];
__device__ int   g_sidx[(size_t)NTOK * NHEAD * TOPK];

// -------- streams/events for the per-head pipeline (host-side, created once
// at load time, before harness mem checkpoints; no device allocations) ------
struct Aux {
    cudaStream_t s2;
    cudaEvent_t evSim[NHEAD];
    cudaEvent_t evDone;
    Aux() {
        cudaStreamCreateWithFlags(&s2, cudaStreamNonBlocking);
        for (int i = 0; i < NHEAD; i++)
            cudaEventCreateWithFlags(&evSim[i], cudaEventDisableTiming);
        cudaEventCreateWithFlags(&evDone, cudaEventDisableTiming);
    }
};
static Aux g_aux;

// ---------------- packed f32x2 helpers ----------------
__device__ __forceinline__ unsigned long long pk2(float lo, float hi) {
    unsigned long long r;
    asm("mov.b64 %0, {%1,%2};" : "=l"(r) : "f"(lo), "f"(hi));
    return r;
}
__device__ __forceinline__ unsigned long long fma2(unsigned long long a,
                                                   unsigned long long b,
                                                   unsigned long long c) {
    unsigned long long d;
    asm("fma.rn.f32x2 %0, %1, %2, %3;" : "=l"(d) : "l"(a), "l"(b), "l"(c));
    return d;
}
__device__ __forceinline__ void unpk2(unsigned long long v, float& lo, float& hi) {
    asm("mov.b64 {%0,%1}, %2;" : "=f"(lo), "=f"(hi) : "l"(v));
}

// ---------------- kernel 1: BN stats -> fold into scale/bias ----------------
__global__ void bn_stats_kernel(const float* __restrict__ X,
                                const float* __restrict__ gamma,
                                const float* __restrict__ beta) {
    int tx = threadIdx.x & 31, ty = threadIdx.x >> 5;
    int col = blockIdx.x * 32 + tx;
    float s = 0.f, ss = 0.f;
    for (int r = ty; r < NTOK; r += 8) {
        float v = X[(size_t)r * DDIM + col];
        s += v; ss += v * v;
    }
    __shared__ float sh[2][8][33];
    sh[0][ty][tx] = s; sh[1][ty][tx] = ss;
    __syncthreads();
    if (ty == 0) {
        float ts = 0.f, tss = 0.f;
#pragma unroll
        for (int i = 0; i < 8; i++) { ts += sh[0][i][tx]; tss += sh[1][i][tx]; }
        float mean = ts * (1.0f / NTOK);
        float var  = tss * (1.0f / NTOK) - mean * mean;
        float rstd = rsqrtf(var + 1e-5f);
        float sc   = gamma[col] * rstd;
        g_cs[col]  = sc;
        g_cb[col]  = beta[col] - mean * sc;
    }
}

// ---------------- kernel 2: qbias = cb @ Wq ----------------
__global__ void qbias_kernel(const float* __restrict__ Wq) {
    int tid = threadIdx.x;
    int jx = tid & 63, ds = tid >> 6;
    int j = blockIdx.x * 64 + jx;
    float acc = 0.f;
    int d0 = ds * 256;
    for (int d = d0; d < d0 + 256; d++)
        acc += g_cb[d] * Wq[(size_t)d * QDIM + j];
    __shared__ float sh[4][64];
    sh[ds][jx] = acc;
    __syncthreads();
    if (ds == 0) g_qbias[j] = sh[0][jx] + sh[1][jx] + sh[2][jx] + sh[3][jx];
}

// ---------------- kernel 2b: transpose keys -> g_kT[(h,p)][kd][key] ---------
__global__ void ktrans_kernel(const float* __restrict__ keys) {
    __shared__ float t[256][17];
    int tid = threadIdx.x;
    int hp = blockIdx.y;
    int h = hp >> 1, p = hp & 1;
    int kd0 = blockIdx.x * 16;
    int kd4 = tid & 3, keyl = tid >> 2;
#pragma unroll
    for (int pass = 0; pass < 4; pass++) {
        int key = pass * 64 + keyl;
        float4 v = *(const float4*)&keys[(size_t)((h * NKEYS + key) * 2 + p) * KDIM + kd0 + kd4 * 4];
        t[key][kd4 * 4 + 0] = v.x;
        t[key][kd4 * 4 + 1] = v.y;
        t[key][kd4 * 4 + 2] = v.z;
        t[key][kd4 * 4 + 3] = v.w;
    }
    __syncthreads();
    int key4 = tid & 63, kdl = tid >> 6;
#pragma unroll
    for (int pass = 0; pass < 4; pass++) {
        int kd = pass * 4 + kdl;
        float4 o;
        o.x = t[key4 * 4 + 0][kd];
        o.y = t[key4 * 4 + 1][kd];
        o.z = t[key4 * 4 + 2][kd];
        o.w = t[key4 * 4 + 3][kd];
        *(float4*)&g_kT[(size_t)(hp * KDIM + kd0 + kd) * NKEYS + key4 * 4] = o;
    }
}

// ---------------- kernel 2c: transpose X -> g_xT[d][token] ------------------
__global__ void xtrans_kernel(const float* __restrict__ X) {
    __shared__ float t[32][33];
    int tid = threadIdx.x;
    int t0 = blockIdx.x * 32, d0 = blockIdx.y * 32;
    int r = tid >> 3, c4 = tid & 7;
    float4 v = *(const float4*)&X[(size_t)(t0 + r) * DDIM + d0 + c4 * 4];
    t[r][c4 * 4 + 0] = v.x;
    t[r][c4 * 4 + 1] = v.y;
    t[r][c4 * 4 + 2] = v.z;
    t[r][c4 * 4 + 3] = v.w;
    __syncthreads();
    float4 o;
    o.x = t[c4 * 4 + 0][r];
    o.y = t[c4 * 4 + 1][r];
    o.z = t[c4 * 4 + 2][r];
    o.w = t[c4 * 4 + 3][r];
    *(float4*)&g_xT[(size_t)(d0 + r) * NTOK + t0 + c4 * 4] = o;
}

// ---------------- kernel 2d: g_wq2 = diag(cs) * Wq --------------------------
__global__ void wscale_kernel(const float* __restrict__ Wq) {
    size_t idx = ((size_t)blockIdx.x * 256 + threadIdx.x) * 4;
    int d = (int)(idx >> 11);
    float s = g_cs[d];
    float4 v = *(const float4*)&Wq[idx];
    v.x *= s; v.y *= s; v.z *= s; v.w *= s;
    *(float4*)&g_wq2[idx] = v;
}

// ---------------- kernel 3: per-head fp32 GEMM (reg-prefetch) ---------------
// grid (2,16): blockIdx.x selects the p-half for head h; bm = blockIdx.y*128.
#define BM 128
#define BN 128
#define BK 16
#define NKT (DDIM / BK)

__global__ void __launch_bounds__(256, 2) gemm_qh_kernel(int h) {
    __shared__ float sA[BK][BM];
    __shared__ float sB[BK][BN];
    int tid = threadIdx.x;
    int ty = tid >> 4, tx = tid & 15;
    int bm = blockIdx.y * BM;
    int bn = (blockIdx.x ? 1024 : 0) + h * KDIM;
    int r0 = tid >> 5, c4 = tid & 31;

    unsigned long long acc[8][4];
#pragma unroll
    for (int i = 0; i < 8; i++)
#pragma unroll
        for (int j = 0; j < 4; j++) acc[i][j] = 0ULL;

    float4 pa[2], pb[2];
#pragma unroll
    for (int l = 0; l < 2; l++) {
        int row = r0 + l * 8;
        pa[l] = *(const float4*)&g_xT[(size_t)row * NTOK + bm + c4 * 4];
        pb[l] = *(const float4*)&g_wq2[(size_t)row * QDIM + bn + c4 * 4];
    }

    for (int kt = 0; kt < NKT; kt++) {
        __syncthreads();
#pragma unroll
        for (int l = 0; l < 2; l++) {
            int row = r0 + l * 8;
            *(float4*)&sA[row][c4 * 4] = pa[l];
            *(float4*)&sB[row][c4 * 4] = pb[l];
        }
        __syncthreads();
        if (kt + 1 < NKT) {
            int k0 = (kt + 1) * BK;
#pragma unroll
            for (int l = 0; l < 2; l++) {
                int row = r0 + l * 8;
                pa[l] = *(const float4*)&g_xT[(size_t)(k0 + row) * NTOK + bm + c4 * 4];
                pb[l] = *(const float4*)&g_wq2[(size_t)(k0 + row) * QDIM + bn + c4 * 4];
            }
        }
#pragma unroll
        for (int k = 0; k < BK; k++) {
            float a[8], b[8];
            *(float4*)&a[0] = *(const float4*)&sA[k][ty * 8];
            *(float4*)&a[4] = *(const float4*)&sA[k][ty * 8 + 4];
            *(float4*)&b[0] = *(const float4*)&sB[k][tx * 8];
            *(float4*)&b[4] = *(const float4*)&sB[k][tx * 8 + 4];
            unsigned long long bp[4];
#pragma unroll
            for (int j = 0; j < 4; j++) bp[j] = pk2(b[2 * j], b[2 * j + 1]);
#pragma unroll
            for (int i = 0; i < 8; i++) {
                unsigned long long ad = pk2(a[i], a[i]);
#pragma unroll
                for (int j = 0; j < 4; j++) acc[i][j] = fma2(ad, bp[j], acc[i][j]);
            }
        }
    }

    int row0 = bm + ty * 8;
#pragma unroll
    for (int j = 0; j < 4; j++) {
        int col0 = bn + tx * 8 + 2 * j;
        float b0 = g_qbias[col0], b1 = g_qbias[col0 + 1];
        float lo[8], hi[8];
#pragma unroll
        for (int i = 0; i < 8; i++) {
            unpk2(acc[i][j], lo[i], hi[i]);
            lo[i] += b0; hi[i] += b1;
        }
        *(float4*)&g_qT[(size_t)col0 * NTOK + row0]           = *(float4*)&lo[0];
        *(float4*)&g_qT[(size_t)col0 * NTOK + row0 + 4]       = *(float4*)&lo[4];
        *(float4*)&g_qT[(size_t)(col0 + 1) * NTOK + row0]     = *(float4*)&hi[0];
        *(float4*)&g_qT[(size_t)(col0 + 1) * NTOK + row0 + 4] = *(float4*)&hi[4];
    }
}

// ---------------- kernel 4: per-head sim + top-16 ----------------
#define TT 32
#define KD_T 32

__device__ __forceinline__ unsigned ford(float f) {
    unsigned b = __float_as_uint(f);
    return b ^ (((unsigned)((int)b >> 31)) | 0x80000000u);
}

__global__ void __launch_bounds__(256, 3) sim_topk_kernel(int h) {
    __shared__ float qt[KD_T * 32];
    __shared__ float kt[KD_T * 256];
    __shared__ float sx_sh[TT * TOPK];
    __shared__ int   ix_sh[TT * TOPK];
    __shared__ float sy_sh[TT * TOPK];
    __shared__ int   iy_sh[TT * TOPK];

    int tid = threadIdx.x;
    int lane = tid & 31, w = tid >> 5;
    int t0 = blockIdx.x * TT;

    int s_kd  = tid >> 3, s_tok4 = tid & 7;
    int s_kdp = tid >> 6, s_key4 = tid & 63;

    float vt[4][8];

    for (int p = 0; p < 2; p++) {
        unsigned long long acc[8][2];
#pragma unroll
        for (int j = 0; j < 8; j++) { acc[j][0] = 0ULL; acc[j][1] = 0ULL; }

        for (int q4 = 0; q4 < 4; q4++) {
            __syncthreads();
            {
                size_t f = (size_t)(p * 1024 + h * KDIM + q4 * KD_T + s_kd);
                float4 v = *(const float4*)&g_qT[f * NTOK + t0 + s_tok4 * 4];
                *(float4*)&qt[s_kd * 32 + s_tok4 * 4] = v;
            }
#pragma unroll
            for (int pass = 0; pass < 8; pass++) {
                int kd = pass * 4 + s_kdp;
                float4 v = *(const float4*)&g_kT[(size_t)((h * 2 + p) * KDIM + q4 * KD_T + kd) * NKEYS + s_key4 * 4];
                *(float4*)&kt[kd * 256 + s_key4 * 4] = v;
            }
            __syncthreads();

            const float* qb = qt + w * 4;
            const float* ka_b = kt + lane * 4;
            const float* kb_b = kt + 128 + lane * 4;
#pragma unroll 4
            for (int kd = 0; kd < KD_T; kd++) {
                float4 qv = *(const float4*)(qb + kd * 32);
                unsigned long long qp01 = pk2(qv.x, qv.y);
                unsigned long long qp23 = pk2(qv.z, qv.w);
                float4 ka = *(const float4*)(ka_b + kd * 256);
                float4 kb = *(const float4*)(kb_b + kd * 256);
                unsigned long long ks[8];
                ks[0] = pk2(ka.x, ka.x); ks[1] = pk2(ka.y, ka.y);
                ks[2] = pk2(ka.z, ka.z); ks[3] = pk2(ka.w, ka.w);
                ks[4] = pk2(kb.x, kb.x); ks[5] = pk2(kb.y, kb.y);
                ks[6] = pk2(kb.z, kb.z); ks[7] = pk2(kb.w, kb.w);
#pragma unroll
                for (int j = 0; j < 8; j++) {
                    acc[j][0] = fma2(qp01, ks[j], acc[j][0]);
                    acc[j][1] = fma2(qp23, ks[j], acc[j][1]);
                }
            }
        }

#pragma unroll
        for (int j = 0; j < 8; j++) {
            unpk2(acc[j][0], vt[0][j], vt[1][j]);
            unpk2(acc[j][1], vt[2][j], vt[3][j]);
        }

#pragma unroll
        for (int rep = 0; rep < 4; rep++) {
            int t = w * 4 + rep;
            for (int it = 0; it < TOPK; it++) {
                float lv = vt[rep][0]; int bj = 0;
#pragma unroll
                for (int j = 1; j < 8; j++)
                    if (vt[rep][j] > lv) { lv = vt[rep][j]; bj = j; }
                unsigned u = ford(lv);
                unsigned m = __reduce_max_sync(0xffffffffu, u);
                unsigned msk = __ballot_sync(0xffffffffu, u == m);
                bool win = (lane == (__ffs(msk) - 1));
#pragma unroll
                for (int j = 0; j < 8; j++)
                    vt[rep][j] = (win && j == bj) ? -INFINITY : vt[rep][j];
                if (win) {
                    int key = (bj >> 2) * 128 + lane * 4 + (bj & 3);
                    if (p == 0) { sx_sh[t * TOPK + it] = lv; ix_sh[t * TOPK + it] = key; }
                    else        { sy_sh[t * TOPK + it] = lv; iy_sh[t * TOPK + it] = key; }
                }
            }
        }
    }
    __syncthreads();

#pragma unroll
    for (int rep = 0; rep < 4; rep++) {
        int t = w * 4 + rep;
        float v[8];
#pragma unroll
        for (int j = 0; j < 8; j++) {
            int cc = j * 32 + lane;
            v[j] = sx_sh[t * TOPK + (cc >> 4)] + sy_sh[t * TOPK + (cc & 15)];
        }
        for (int it = 0; it < TOPK; it++) {
            float lv = v[0]; int bj = 0;
#pragma unroll
            for (int j = 1; j < 8; j++)
                if (v[j] > lv) { lv = v[j]; bj = j; }
            unsigned u = ford(lv);
            unsigned m = __reduce_max_sync(0xffffffffu, u);
            unsigned msk = __ballot_sync(0xffffffffu, u == m);
            bool win = (lane == (__ffs(msk) - 1));
#pragma unroll
            for (int j = 0; j < 8; j++)
                v[j] = (win && j == bj) ? -INFINITY : v[j];
            if (win) {
                int bi = bj * 32 + lane;
                int expert = ix_sh[t * TOPK + (bi >> 4)] * NKEYS + iy_sh[t * TOPK + (bi & 15)];
                size_t o = ((size_t)(t0 + t) * NHEAD + h) * TOPK + it;
                g_scores[o] = lv;
                g_sidx[o]   = expert;
            }
        }
    }
}

// ---------------- kernel 5: per-head expert gather/accumulate ---------------
// 16 experts for head h per token; h==0 writes out, h>0 accumulates.
// expertH launches are stream-serialized, so the read-modify-write is safe.
__global__ void __launch_bounds__(512) expertH_kernel(int h,
                                                      const float* __restrict__ X,
                                                      const float* __restrict__ down_w,
                                                      const float* __restrict__ up_w,
                                                      float* __restrict__ out) {
    __shared__ float xin[DDIM];
    __shared__ float hsh[16];
    __shared__ int   isha[16];
    __shared__ float ssh[16];
    int t = blockIdx.x, tid = threadIdx.x;
    *(float2*)&xin[tid * 2] = *(const float2*)&X[(size_t)t * DDIM + tid * 2];
    if (tid < 16) {
        isha[tid] = g_sidx[(size_t)t * 128 + h * 16 + tid];
        ssh[tid]  = g_scores[(size_t)t * 128 + h * 16 + tid];
    }
    __syncthreads();

    int w = tid >> 5, lane = tid & 31;   // 16 warps, warp w -> expert slot w
    const float4* xin4 = (const float4*)xin;
    {
        const float4* wr = (const float4*)(down_w + (size_t)isha[w] * DDIM);
        float acc = 0.f;
#pragma unroll
        for (int i = 0; i < 8; i++) {
            float4 a = wr[lane + i * 32];
            float4 b = xin4[lane + i * 32];
            acc += a.x * b.x + a.y * b.y + a.z * b.z + a.w * b.w;
        }
#pragma unroll
        for (int off = 16; off; off >>= 1) acc += __shfl_down_sync(0xffffffffu, acc, off);
        if (lane == 0) hsh[w] = acc;
    }
    __syncthreads();
    if (tid < 16) {
        float hv = hsh[tid];
        float g  = 0.5f * hv * (1.0f + erff(hv * 0.70710678118654752f));  // exact GELU
        float sg = 1.0f / (1.0f + expf(-ssh[tid]));
        hsh[tid] = g * sg;
    }
    __syncthreads();
    int c = tid * 2;
    float accx = 0.f, accy = 0.f;
#pragma unroll 4
    for (int e = 0; e < 16; e++) {
        float2 uw = *(const float2*)(up_w + (size_t)isha[e] * DDIM + c);
        float hv = hsh[e];
        accx += hv * uw.x;
        accy += hv * uw.y;
    }
    float2 o;
    if (h == 0) {
        o.x = accx; o.y = accy;
    } else {
        float2 cur = *(const float2*)&out[(size_t)t * DDIM + c];
        o.x = cur.x + accx; o.y = cur.y + accy;
    }
    *(float2*)&out[(size_t)t * DDIM + c] = o;
}

// ---------------- launch ----------------
extern "C" void kernel_launch(void* const* d_in, const int* in_sizes, int n_in,
                              void* d_out, int out_size) {
    const float* X      = (const float*)d_in[0];
    const float* gamma  = (const float*)d_in[1];
    const float* beta   = (const float*)d_in[2];
    const float* Wq     = (const float*)d_in[3];
    const float* keys   = (const float*)d_in[4];
    const float* down_w = (const float*)d_in[5];
    const float* up_w   = (const float*)d_in[6];
    float* out = (float*)d_out;

    // prep (capture stream)
    bn_stats_kernel<<<32, 256>>>(X, gamma, beta);
    qbias_kernel<<<32, 256>>>(Wq);
    wscale_kernel<<<2048, 256>>>(Wq);
    xtrans_kernel<<<dim3(NTOK / 32, DDIM / 32), 256>>>(X);
    ktrans_kernel<<<dim3(8, 16), 256>>>(keys);

    // per-head pipeline: stream 0 = gemm+sim, s2 = expert (BW-bound), overlapped
    for (int h = 0; h < NHEAD; h++) {
        gemm_qh_kernel<<<dim3(2, 16), 256>>>(h);
        sim_topk_kernel<<<64, 256>>>(h);
        cudaEventRecord(g_aux.evSim[h], 0);
        cudaStreamWaitEvent(g_aux.s2, g_aux.evSim[h], 0);
        expertH_kernel<<<NTOK, 512, 0, g_aux.s2>>>(h, X, down_w, up_w, out);
    }
    cudaEventRecord(g_aux.evDone, g_aux.s2);
    cudaStreamWaitEvent(0, g_aux.evDone, 0);
}

// round 16
// speedup vs baseline: 3.4513x; 3.4513x over previous
#include <cuda_runtime.h>
#include <cuda_bf16.h>
#include <math.h>
#include <stdint.h>

// Problem constants
#define NTOK   2048       // B*N
#define DDIM   1024
#define QDIM   2048       // 2*H*KD
#define NHEAD  8
#define KDIM   128
#define NKEYS  256
#define TOPK   16

// -------- scratch (device globals; no runtime allocation) --------
__device__ float g_cs[DDIM];          // per-col scale  = gamma * rstd
__device__ float g_cb[DDIM];          // per-col bias   = beta - mean*gamma*rstd
__device__ float g_qbias[QDIM];       // c @ Wq
__device__ float g_xT[(size_t)DDIM * NTOK];       // 8 MB, X transposed [d][token]
__device__ float g_wq2[(size_t)DDIM * QDIM];      // 8 MB, diag(cs)*Wq
__device__ float g_qT[(size_t)QDIM * NTOK];       // 16 MB, [feature][token]
__device__ float g_kT[(size_t)NHEAD * 2 * KDIM * NKEYS];  // 2 MB, [(h,p)][kd][key]
__device__ float g_scores[(size_t)NTOK * NHEAD * TOPK];
__device__ int   g_sidx[(size_t)NTOK * NHEAD * TOPK];

// ---------------- packed f32x2 helpers ----------------
__device__ __forceinline__ unsigned long long pk2(float lo, float hi) {
    unsigned long long r;
    asm("mov.b64 %0, {%1,%2};" : "=l"(r) : "f"(lo), "f"(hi));
    return r;
}
__device__ __forceinline__ unsigned long long fma2(unsigned long long a,
                                                   unsigned long long b,
                                                   unsigned long long c) {
    unsigned long long d;
    asm("fma.rn.f32x2 %0, %1, %2, %3;" : "=l"(d) : "l"(a), "l"(b), "l"(c));
    return d;
}
__device__ __forceinline__ void unpk2(unsigned long long v, float& lo, float& hi) {
    asm("mov.b64 {%0,%1}, %2;" : "=f"(lo), "=f"(hi) : "l"(v));
}

// ---------------- kernel 1: BN stats -> fold into scale/bias ----------------
__global__ void bn_stats_kernel(const float* __restrict__ X,
                                const float* __restrict__ gamma,
                                const float* __restrict__ beta) {
    int tx = threadIdx.x & 31, ty = threadIdx.x >> 5;   // ty in 0..7
    int col = blockIdx.x * 32 + tx;
    float s = 0.f, ss = 0.f;
    for (int r = ty; r < NTOK; r += 8) {
        float v = X[(size_t)r * DDIM + col];
        s += v; ss += v * v;
    }
    __shared__ float sh[2][8][33];
    sh[0][ty][tx] = s; sh[1][ty][tx] = ss;
    __syncthreads();
    if (ty == 0) {
        float ts = 0.f, tss = 0.f;
#pragma unroll
        for (int i = 0; i < 8; i++) { ts += sh[0][i][tx]; tss += sh[1][i][tx]; }
        float mean = ts * (1.0f / NTOK);
        float var  = tss * (1.0f / NTOK) - mean * mean;
        float rstd = rsqrtf(var + 1e-5f);
        float sc   = gamma[col] * rstd;
        g_cs[col]  = sc;
        g_cb[col]  = beta[col] - mean * sc;
    }
}

// ---------------- kernel 2: qbias = cb @ Wq ----------------
__global__ void qbias_kernel(const float* __restrict__ Wq) {
    int tid = threadIdx.x;
    int jx = tid & 63, ds = tid >> 6;
    int j = blockIdx.x * 64 + jx;
    float acc = 0.f;
    int d0 = ds * 256;
    for (int d = d0; d < d0 + 256; d++)
        acc += g_cb[d] * Wq[(size_t)d * QDIM + j];
    __shared__ float sh[4][64];
    sh[ds][jx] = acc;
    __syncthreads();
    if (ds == 0) g_qbias[j] = sh[0][jx] + sh[1][jx] + sh[2][jx] + sh[3][jx];
}

// ---------------- kernel 2b: transpose keys -> g_kT[(h,p)][kd][key] ---------
__global__ void ktrans_kernel(const float* __restrict__ keys) {
    __shared__ float t[256][17];
    int tid = threadIdx.x;
    int hp = blockIdx.y;                 // h*2 + p
    int h = hp >> 1, p = hp & 1;
    int kd0 = blockIdx.x * 16;
    int kd4 = tid & 3, keyl = tid >> 2;  // keyl 0..63
#pragma unroll
    for (int pass = 0; pass < 4; pass++) {
        int key = pass * 64 + keyl;
        float4 v = *(const float4*)&keys[(size_t)((h * NKEYS + key) * 2 + p) * KDIM + kd0 + kd4 * 4];
        t[key][kd4 * 4 + 0] = v.x;
        t[key][kd4 * 4 + 1] = v.y;
        t[key][kd4 * 4 + 2] = v.z;
        t[key][kd4 * 4 + 3] = v.w;
    }
    __syncthreads();
    int key4 = tid & 63, kdl = tid >> 6;
#pragma unroll
    for (int pass = 0; pass < 4; pass++) {
        int kd = pass * 4 + kdl;
        float4 o;
        o.x = t[key4 * 4 + 0][kd];
        o.y = t[key4 * 4 + 1][kd];
        o.z = t[key4 * 4 + 2][kd];
        o.w = t[key4 * 4 + 3][kd];
        *(float4*)&g_kT[(size_t)(hp * KDIM + kd0 + kd) * NKEYS + key4 * 4] = o;
    }
}

// ---------------- kernel 2c: transpose X -> g_xT[d][token] ------------------
__global__ void xtrans_kernel(const float* __restrict__ X) {
    __shared__ float t[32][33];
    int tid = threadIdx.x;
    int t0 = blockIdx.x * 32, d0 = blockIdx.y * 32;
    int r = tid >> 3, c4 = tid & 7;      // 32 rows x 8 float4
    float4 v = *(const float4*)&X[(size_t)(t0 + r) * DDIM + d0 + c4 * 4];
    t[r][c4 * 4 + 0] = v.x;
    t[r][c4 * 4 + 1] = v.y;
    t[r][c4 * 4 + 2] = v.z;
    t[r][c4 * 4 + 3] = v.w;
    __syncthreads();
    float4 o;
    o.x = t[c4 * 4 + 0][r];
    o.y = t[c4 * 4 + 1][r];
    o.z = t[c4 * 4 + 2][r];
    o.w = t[c4 * 4 + 3][r];
    *(float4*)&g_xT[(size_t)(d0 + r) * NTOK + t0 + c4 * 4] = o;
}

// ---------------- kernel 2d: g_wq2 = diag(cs) * Wq --------------------------
__global__ void wscale_kernel(const float* __restrict__ Wq) {
    size_t idx = ((size_t)blockIdx.x * 256 + threadIdx.x) * 4;
    int d = (int)(idx >> 11);            // / QDIM
    float s = g_cs[d];
    float4 v = *(const float4*)&Wq[idx];
    v.x *= s; v.y *= s; v.z *= s; v.w *= s;
    *(float4*)&g_wq2[idx] = v;
}

// ---------------- kernel 3: fp32 GEMM, reg-prefetch + double-buffered smem --
// C[t][j] = sum_d g_xT[d][t] * g_wq2[d][j] + qbias[j], stored to g_qT[j][t].
// BM=BN=128, BK=16, 256 threads, 8x8 f32x2 tile. One __syncthreads per tile:
// STS targets the buffer whose readers passed the PREVIOUS barrier.
#define BM 128
#define BN 128
#define BK 16
#define NKT (DDIM / BK)

__global__ void __launch_bounds__(256, 2) gemm_q_kernel() {
    __shared__ float sA[2][BK][BM];   // ping-pong
    __shared__ float sB[2][BK][BN];
    int tid = threadIdx.x;
    int ty = tid >> 4, tx = tid & 15;
    int bm = blockIdx.y * BM;
    int bn = blockIdx.x * BN;
    int r0 = tid >> 5, c4 = tid & 31;     // staging rows r0, r0+8; col c4*4

    unsigned long long acc[8][4];
#pragma unroll
    for (int i = 0; i < 8; i++)
#pragma unroll
        for (int j = 0; j < 4; j++) acc[i][j] = 0ULL;

    float4 pa[2], pb[2];
    // tile 0 -> regs -> smem[0]
#pragma unroll
    for (int l = 0; l < 2; l++) {
        int row = r0 + l * 8;
        pa[l] = *(const float4*)&g_xT[(size_t)row * NTOK + bm + c4 * 4];
        pb[l] = *(const float4*)&g_wq2[(size_t)row * QDIM + bn + c4 * 4];
    }
#pragma unroll
    for (int l = 0; l < 2; l++) {
        int row = r0 + l * 8;
        *(float4*)&sA[0][row][c4 * 4] = pa[l];
        *(float4*)&sB[0][row][c4 * 4] = pb[l];
    }
    __syncthreads();

    for (int kt = 0; kt < NKT; kt++) {
        int cur = kt & 1, nxt = cur ^ 1;
        // prefetch next tile into regs (LDG latency overlaps compute below)
        if (kt + 1 < NKT) {
            int k0 = (kt + 1) * BK;
#pragma unroll
            for (int l = 0; l < 2; l++) {
                int row = r0 + l * 8;
                pa[l] = *(const float4*)&g_xT[(size_t)(k0 + row) * NTOK + bm + c4 * 4];
                pb[l] = *(const float4*)&g_wq2[(size_t)(k0 + row) * QDIM + bn + c4 * 4];
            }
        }
#pragma unroll
        for (int k = 0; k < BK; k++) {
            float a[8], b[8];
            *(float4*)&a[0] = *(const float4*)&sA[cur][k][ty * 8];
            *(float4*)&a[4] = *(const float4*)&sA[cur][k][ty * 8 + 4];
            *(float4*)&b[0] = *(const float4*)&sB[cur][k][tx * 8];
            *(float4*)&b[4] = *(const float4*)&sB[cur][k][tx * 8 + 4];
            unsigned long long bp[4];
#pragma unroll
            for (int j = 0; j < 4; j++) bp[j] = pk2(b[2 * j], b[2 * j + 1]);
#pragma unroll
            for (int i = 0; i < 8; i++) {
                unsigned long long ad = pk2(a[i], a[i]);
#pragma unroll
                for (int j = 0; j < 4; j++) acc[i][j] = fma2(ad, bp[j], acc[i][j]);
            }
        }
        if (kt + 1 < NKT) {
            // write next tile into the other buffer; its previous readers
            // finished before the last barrier, so this store is safe now.
#pragma unroll
            for (int l = 0; l < 2; l++) {
                int row = r0 + l * 8;
                *(float4*)&sA[nxt][row][c4 * 4] = pa[l];
                *(float4*)&sB[nxt][row][c4 * 4] = pb[l];
            }
            __syncthreads();
        }
    }

    // epilogue: + qbias, store TRANSPOSED into g_qT[feature][token]
    int row0 = bm + ty * 8;
#pragma unroll
    for (int j = 0; j < 4; j++) {
        int col0 = bn + tx * 8 + 2 * j;
        float b0 = g_qbias[col0], b1 = g_qbias[col0 + 1];
        float lo[8], hi[8];
#pragma unroll
        for (int i = 0; i < 8; i++) {
            unpk2(acc[i][j], lo[i], hi[i]);
            lo[i] += b0; hi[i] += b1;
        }
        *(float4*)&g_qT[(size_t)col0 * NTOK + row0]           = *(float4*)&lo[0];
        *(float4*)&g_qT[(size_t)col0 * NTOK + row0 + 4]       = *(float4*)&lo[4];
        *(float4*)&g_qT[(size_t)(col0 + 1) * NTOK + row0]     = *(float4*)&hi[0];
        *(float4*)&g_qT[(size_t)(col0 + 1) * NTOK + row0 + 4] = *(float4*)&hi[4];
    }
}

// ---------------- kernel 4: sim + top-16 v3 ----------------
#define TT 32
#define KD_T 32

__device__ __forceinline__ unsigned ford(float f) {
    unsigned b = __float_as_uint(f);
    return b ^ (((unsigned)((int)b >> 31)) | 0x80000000u);
}

__global__ void __launch_bounds__(256, 3) sim_topk_kernel() {
    __shared__ float qt[KD_T * 32];        // [kd][token]
    __shared__ float kt[KD_T * 256];       // [kd][key]
    __shared__ float sx_sh[TT * TOPK];
    __shared__ int   ix_sh[TT * TOPK];
    __shared__ float sy_sh[TT * TOPK];
    __shared__ int   iy_sh[TT * TOPK];

    int tid = threadIdx.x;
    int lane = tid & 31, w = tid >> 5;     // 8 warps
    int h = blockIdx.y;
    int t0 = blockIdx.x * TT;

    int s_kd  = tid >> 3, s_tok4 = tid & 7;     // qt stage
    int s_kdp = tid >> 6, s_key4 = tid & 63;    // kt stage

    float vt[4][8];

    for (int p = 0; p < 2; p++) {
        unsigned long long acc[8][2];
#pragma unroll
        for (int j = 0; j < 8; j++) { acc[j][0] = 0ULL; acc[j][1] = 0ULL; }

        for (int q4 = 0; q4 < 4; q4++) {
            __syncthreads();
            {
                size_t f = (size_t)(p * 1024 + h * KDIM + q4 * KD_T + s_kd);
                float4 v = *(const float4*)&g_qT[f * NTOK + t0 + s_tok4 * 4];
                *(float4*)&qt[s_kd * 32 + s_tok4 * 4] = v;
            }
#pragma unroll
            for (int pass = 0; pass < 8; pass++) {
                int kd = pass * 4 + s_kdp;
                float4 v = *(const float4*)&g_kT[(size_t)((h * 2 + p) * KDIM + q4 * KD_T + kd) * NKEYS + s_key4 * 4];
                *(float4*)&kt[kd * 256 + s_key4 * 4] = v;
            }
            __syncthreads();

            const float* qb = qt + w * 4;
            const float* ka_b = kt + lane * 4;
            const float* kb_b = kt + 128 + lane * 4;
#pragma unroll 4
            for (int kd = 0; kd < KD_T; kd++) {
                float4 qv = *(const float4*)(qb + kd * 32);
                unsigned long long qp01 = pk2(qv.x, qv.y);
                unsigned long long qp23 = pk2(qv.z, qv.w);
                float4 ka = *(const float4*)(ka_b + kd * 256);
                float4 kb = *(const float4*)(kb_b + kd * 256);
                unsigned long long ks[8];
                ks[0] = pk2(ka.x, ka.x); ks[1] = pk2(ka.y, ka.y);
                ks[2] = pk2(ka.z, ka.z); ks[3] = pk2(ka.w, ka.w);
                ks[4] = pk2(kb.x, kb.x); ks[5] = pk2(kb.y, kb.y);
                ks[6] = pk2(kb.z, kb.z); ks[7] = pk2(kb.w, kb.w);
#pragma unroll
                for (int j = 0; j < 8; j++) {
                    acc[j][0] = fma2(qp01, ks[j], acc[j][0]);
                    acc[j][1] = fma2(qp23, ks[j], acc[j][1]);
                }
            }
        }

#pragma unroll
        for (int j = 0; j < 8; j++) {
            unpk2(acc[j][0], vt[0][j], vt[1][j]);
            unpk2(acc[j][1], vt[2][j], vt[3][j]);
        }

#pragma unroll
        for (int rep = 0; rep < 4; rep++) {
            int t = w * 4 + rep;
            for (int it = 0; it < TOPK; it++) {
                float lv = vt[rep][0]; int bj = 0;
#pragma unroll
                for (int j = 1; j < 8; j++)
                    if (vt[rep][j] > lv) { lv = vt[rep][j]; bj = j; }
                unsigned u = ford(lv);
                unsigned m = __reduce_max_sync(0xffffffffu, u);
                unsigned msk = __ballot_sync(0xffffffffu, u == m);
                bool win = (lane == (__ffs(msk) - 1));
#pragma unroll
                for (int j = 0; j < 8; j++)
                    vt[rep][j] = (win && j == bj) ? -INFINITY : vt[rep][j];
                if (win) {
                    int key = (bj >> 2) * 128 + lane * 4 + (bj & 3);
                    if (p == 0) { sx_sh[t * TOPK + it] = lv; ix_sh[t * TOPK + it] = key; }
                    else        { sy_sh[t * TOPK + it] = lv; iy_sh[t * TOPK + it] = key; }
                }
            }
        }
    }
    __syncthreads();

#pragma unroll
    for (int rep = 0; rep < 4; rep++) {
        int t = w * 4 + rep;
        float v[8];
#pragma unroll
        for (int j = 0; j < 8; j++) {
            int cc = j * 32 + lane;
            v[j] = sx_sh[t * TOPK + (cc >> 4)] + sy_sh[t * TOPK + (cc & 15)];
        }
        for (int it = 0; it < TOPK; it++) {
            float lv = v[0]; int bj = 0;
#pragma unroll
            for (int j = 1; j < 8; j++)
                if (v[j] > lv) { lv = v[j]; bj = j; }
            unsigned u = ford(lv);
            unsigned m = __reduce_max_sync(0xffffffffu, u);
            unsigned msk = __ballot_sync(0xffffffffu, u == m);
            bool win = (lane == (__ffs(msk) - 1));
#pragma unroll
            for (int j = 0; j < 8; j++)
                v[j] = (win && j == bj) ? -INFINITY : v[j];
            if (win) {
                int bi = bj * 32 + lane;
                int expert = ix_sh[t * TOPK + (bi >> 4)] * NKEYS + iy_sh[t * TOPK + (bi & 15)];
                size_t o = ((size_t)(t0 + t) * NHEAD + h) * TOPK + it;
                g_scores[o] = lv;
                g_sidx[o]   = expert;
            }
        }
    }
}

// ---------------- kernel 5: expert gather / down-dot / act / up-accumulate ----
__global__ void __launch_bounds__(512) expert_kernel(const float* __restrict__ X,
                                                     const float* __restrict__ down_w,
                                                     const float* __restrict__ up_w,
                                                     float* __restrict__ out) {
    __shared__ float xin[DDIM];
    __shared__ float hsh[128];
    __shared__ int   isha[128];
    __shared__ float ssh[128];
    int t = blockIdx.x, tid = threadIdx.x;
    *(float2*)&xin[tid * 2] = *(const float2*)&X[(size_t)t * DDIM + tid * 2];
    if (tid < 128) {
        isha[tid] = g_sidx[(size_t)t * 128 + tid];
        ssh[tid]  = g_scores[(size_t)t * 128 + tid];
    }
    __syncthreads();

    int w = tid >> 5, lane = tid & 31;
    const float4* xin4 = (const float4*)xin;
    for (int e = w; e < 128; e += 16) {
        const float4* wr = (const float4*)(down_w + (size_t)isha[e] * DDIM);
        float acc = 0.f;
#pragma unroll
        for (int i = 0; i < 8; i++) {
            float4 a = wr[lane + i * 32];
            float4 b = xin4[lane + i * 32];
            acc += a.x * b.x + a.y * b.y + a.z * b.z + a.w * b.w;
        }
#pragma unroll
        for (int off = 16; off; off >>= 1) acc += __shfl_down_sync(0xffffffffu, acc, off);
        if (lane == 0) hsh[e] = acc;
    }
    __syncthreads();
    if (tid < 128) {
        float hv = hsh[tid];
        float g  = 0.5f * hv * (1.0f + erff(hv * 0.70710678118654752f));  // exact GELU
        float sg = 1.0f / (1.0f + expf(-ssh[tid]));
        hsh[tid] = g * sg;
    }
    __syncthreads();
    int c = tid * 2;
    float accx = 0.f, accy = 0.f;
#pragma unroll 8
    for (int e = 0; e < 128; e++) {
        float2 uw = *(const float2*)(up_w + (size_t)isha[e] * DDIM + c);
        float hv = hsh[e];
        accx += hv * uw.x;
        accy += hv * uw.y;
    }
    float2 o; o.x = accx; o.y = accy;
    *(float2*)&out[(size_t)t * DDIM + c] = o;
}

// ---------------- launch ----------------
extern "C" void kernel_launch(void* const* d_in, const int* in_sizes, int n_in,
                              void* d_out, int out_size) {
    const float* X      = (const float*)d_in[0];
    const float* gamma  = (const float*)d_in[1];
    const float* beta   = (const float*)d_in[2];
    const float* Wq     = (const float*)d_in[3];
    const float* keys   = (const float*)d_in[4];
    const float* down_w = (const float*)d_in[5];
    const float* up_w   = (const float*)d_in[6];
    float* out = (float*)d_out;

    bn_stats_kernel<<<32, 256>>>(X, gamma, beta);
    qbias_kernel<<<32, 256>>>(Wq);
    wscale_kernel<<<2048, 256>>>(Wq);
    xtrans_kernel<<<dim3(NTOK / 32, DDIM / 32), 256>>>(X);
    ktrans_kernel<<<dim3(8, 16), 256>>>(keys);

    gemm_q_kernel<<<dim3(QDIM / BN, NTOK / BM), 256>>>();

    sim_topk_kernel<<<dim3(NTOK / TT, NHEAD), 256>>>();

    expert_kernel<<<NTOK, 512>>>(X, down_w, up_w, out);
}